// round 15
// baseline (speedup 1.0000x reference)
#include <cuda_runtime.h>
#include <cstdint>

// ---------------------------------------------------------------------------
// SphericalExpansion, round 15: gather (no output atomics) with the pointer
// chase HIDDEN: 4 interleaved chains per warp (MLP=4 on the dependent loads).
//
//   K1: per edge, seg = 4*idx_i + z[idx_j];
//       next[e] = atomicExch(&head[seg], e+1)   (0 = empty; e+1 encoding)
//       -> __device__ globals start zeroed; K2 resets heads to 0 after use,
//          so every graph replay sees identical initial state. NO init kernel.
//   K2: warp owns segments 4g..4g+3; walks all 4 chains concurrently with
//       branch-free predication (warp-uniform selects, no BSSY per edge).
//       Lane L owns floats {L,L+32,L+64,L+96} of each segment (lm=L&15,
//       n=(L>>4)+2k), accumulates in registers; 1 exp + compact-Y + 4 shfl
//       + 4 FMA per (chain,edge); epilogue: 16 coalesced 128B stores + head
//       reset. Covers empty segments (writes zeros) -> no zero-fill kernel.
// ---------------------------------------------------------------------------

#define NSEG_MAX 80000     // N_ATOMS * N_SPECIES
#define J_MAX    800000    // N_EDGES

__device__ int g_head[NSEG_MAX];   // e+1, 0 = empty (zero-init at load)
__device__ int g_next[J_MAX];      // e+1 or 0

// f1 selector: 0 = 1, 1 = x, 2 = y, 3 = z
__constant__ int cFS[16] = {0,2,3,1, 0,0,0,0, 0,2,1,2, 3,1,3,1};
// P,Q selectors for U1 = P*Q: 0 = x, 1 = y, 2 = z
__constant__ int cPQ[16][2] = {
    {0,0},{0,0},{0,0},{0,0},
    {0,1},{1,2},{0,0},{2,0},
    {0,0},{0,0},{1,2},{0,0},
    {0,0},{0,0},{0,0},{0,0},
};
// {C0, C1, C2}: Y = f1 * (C0 + C1*(P*Q) + C2*z2)  (y^2 removed via unit norm)
__constant__ float cC[16][3] = {
    { 0.28209479177387814f, 0.f,                 0.f},
    { 0.4886025119029199f,  0.f,                 0.f},
    { 0.4886025119029199f,  0.f,                 0.f},
    { 0.4886025119029199f,  0.f,                 0.f},
    { 0.f,                  1.0925484305920792f, 0.f},
    { 0.f,                  1.0925484305920792f, 0.f},
    {-0.31539156525252005f, 0.f,                 0.9461746957575602f},
    { 0.f,                  1.0925484305920792f, 0.f},
    {-0.5462742152960396f,  1.0925484305920792f, 0.5462742152960396f},
    {-0.5900435899266435f,  2.360174359706574f,  0.5900435899266435f},
    { 0.f,                  2.890611442640554f,  0.f},
    {-0.4570457994644658f,  0.f,                 2.285228997322329f},
    {-1.1195289977703462f,  0.f,                 1.865881662950577f},
    {-0.4570457994644658f,  0.f,                 2.285228997322329f},
    {-1.445305721320277f,   2.890611442640554f,  1.445305721320277f},
    {-1.7701307697799304f,  2.360174359706574f,  1.7701307697799304f},
};
__constant__ int cLM2L[16] = {0,1,1,1, 2,2,2,2, 2,3,3,3, 3,3,3,3};

#define K2E (-2.8853900817779268f)   // -2*log2(e)

__device__ __forceinline__ float ex2(float a) {
    float r; asm("ex2.approx.f32 %0, %1;" : "=f"(r) : "f"(a)); return r;
}
__device__ __forceinline__ float cutoff(float r) {
    const float u = __saturatef(fmaf(r, 2.0f, -9.0f));
    return fmaf(cospif(u), 0.5f, 0.5f);
}

// ---- K1: bucket edges into per-segment linked lists (4 edges/thread) ----
__global__ void __launch_bounds__(256) build_lists_kernel(
    const int* __restrict__ zspec,
    const int* __restrict__ idx_i,
    const int* __restrict__ idx_j,
    int J)
{
    const int tq = blockIdx.x * blockDim.x + threadIdx.x;   // quad index
    const int e0 = tq << 2;
    if (e0 + 3 < J) {
        const int4 i4 = __ldg((const int4*)idx_i + tq);
        const int4 j4 = __ldg((const int4*)idx_j + tq);
        const int s0 = (i4.x << 2) + __ldg(zspec + j4.x);
        const int s1 = (i4.y << 2) + __ldg(zspec + j4.y);
        const int s2 = (i4.z << 2) + __ldg(zspec + j4.z);
        const int s3 = (i4.w << 2) + __ldg(zspec + j4.w);
        int4 nx;
        nx.x = atomicExch(&g_head[s0], e0 + 1);
        nx.y = atomicExch(&g_head[s1], e0 + 2);
        nx.z = atomicExch(&g_head[s2], e0 + 3);
        nx.w = atomicExch(&g_head[s3], e0 + 4);
        *((int4*)g_next + tq) = nx;
    } else {
        for (int e = e0; e < J; e++) {
            const int s = (__ldg(idx_i + e) << 2) + __ldg(zspec + __ldg(idx_j + e));
            g_next[e] = atomicExch(&g_head[s], e + 1);
        }
    }
}

// ---- K2: 4 interleaved chains per warp, register accumulation ----
__global__ void __launch_bounds__(256) gather_kernel(
    const float* __restrict__ dist,
    const float* __restrict__ dirs,      // [J,3]
    const float* __restrict__ centers,   // [32]
    float*       __restrict__ out,       // [nseg * 128]
    int nseg)
{
    const int lane  = threadIdx.x & 31;
    const int warp  = (blockIdx.x * blockDim.x + threadIdx.x) >> 5;
    const int nwarp = (gridDim.x * blockDim.x) >> 5;

    const int lm = lane & 15;
    const int h  = lane >> 4;
    const int l  = cLM2L[lm];

    const float cen = centers[lane];
    const float C0 = cC[lm][0], C1 = cC[lm][1], C2 = cC[lm][2];
    const int fs = cFS[lm];
    const int pi = cPQ[lm][0], qi = cPQ[lm][1];
    const bool f_y = (fs == 2), f_z = (fs == 3), f_one = (fs == 0);
    const bool p_y = (pi == 1), p_z = (pi == 2);
    const bool q_y = (qi == 1), q_z = (qi == 2);

    const int sR0 = 8*l + h;
    const int sR1 = sR0 + 2;
    const int sR2 = sR0 + 4;
    const int sR3 = sR0 + 6;

    const unsigned msk = 0xffffffffu;
    const int ngrp = nseg >> 2;          // 4 segments per warp-group

    for (int g = warp; g < ngrp; g += nwarp) {
        const int s0 = g << 2;

        int ec[4];
        ec[0] = g_head[s0 + 0];
        ec[1] = g_head[s0 + 1];
        ec[2] = g_head[s0 + 2];
        ec[3] = g_head[s0 + 3];

        float acc[4][4];
        #pragma unroll
        for (int c = 0; c < 4; c++)
            acc[c][0] = acc[c][1] = acc[c][2] = acc[c][3] = 0.f;

        while (__any_sync(msk, (ec[0] | ec[1] | ec[2] | ec[3]) != 0)) {
            #pragma unroll
            for (int c = 0; c < 4; c++) {
                const bool v  = (ec[c] != 0);            // warp-uniform
                const int idx = v ? ec[c] - 1 : 0;

                const int   en = __ldg(g_next + idx);
                const float r  = __ldg(dist + idx);
                const float x  = __ldg(dirs + 3*idx + 0);
                const float y  = __ldg(dirs + 3*idx + 1);
                const float z  = __ldg(dirs + 3*idx + 2);

                // rb for this lane's center (zeroed for inactive chain)
                const float t   = r - cen;
                float rb = ex2(K2E * t * t) * cutoff(r);
                rb = v ? rb : 0.f;

                // Y = f1 * (C0 + C1*P*Q + C2*z^2)
                const float Pv = p_y ? y : (p_z ? z : x);
                const float Qv = q_y ? y : (q_z ? z : x);
                const float f2 = fmaf(C1, Pv * Qv, fmaf(C2, z * z, C0));
                const float F1 = f_y ? y : (f_z ? z : x);
                const float Y  = f_one ? f2 : F1 * f2;

                const float R0 = __shfl_sync(msk, rb, sR0);
                const float R1 = __shfl_sync(msk, rb, sR1);
                const float R2 = __shfl_sync(msk, rb, sR2);
                const float R3 = __shfl_sync(msk, rb, sR3);

                acc[c][0] = fmaf(Y, R0, acc[c][0]);
                acc[c][1] = fmaf(Y, R1, acc[c][1]);
                acc[c][2] = fmaf(Y, R2, acc[c][2]);
                acc[c][3] = fmaf(Y, R3, acc[c][3]);

                ec[c] = v ? en : 0;
            }
        }

        // epilogue: 16 coalesced 128B stores + head reset (for next replay)
        #pragma unroll
        for (int c = 0; c < 4; c++) {
            float* p = out + ((size_t)(s0 + c) << 7) + lane;
            p[0]  = acc[c][0];
            p[32] = acc[c][1];
            p[64] = acc[c][2];
            p[96] = acc[c][3];
        }
        if (lane < 4) g_head[s0 + lane] = 0;
    }
}

extern "C" void kernel_launch(void* const* d_in, const int* in_sizes, int n_in,
                              void* d_out, int out_size) {
    const float* dist    = (const float*)d_in[0];
    const float* dirs    = (const float*)d_in[1];
    const float* centers = (const float*)d_in[2];
    const int*   zspec   = (const int*)d_in[3];
    const int*   idx_i   = (const int*)d_in[4];
    const int*   idx_j   = (const int*)d_in[5];
    float*       out     = (float*)d_out;
    const int J    = in_sizes[0];
    const int nseg = out_size >> 7;      // 128 floats per segment

    // K1: bucket edges (4/thread, int4 loads + int4 next store)
    const int nquad = (J + 3) >> 2;
    build_lists_kernel<<<(nquad + 255) / 256, 256>>>(zspec, idx_i, idx_j, J);

    // K2: gather — one resident wave at actual occupancy
    int nsm = 148, occ = 6;
    cudaDeviceGetAttribute(&nsm, cudaDevAttrMultiProcessorCount, 0);
    cudaOccupancyMaxActiveBlocksPerMultiprocessor(&occ, gather_kernel, 256, 0);
    if (occ < 1) occ = 1;
    gather_kernel<<<nsm * occ, 256>>>(dist, dirs, centers, out, nseg);
}

// round 16
// speedup vs baseline: 1.1792x; 1.1792x over previous
#include <cuda_runtime.h>
#include <cstdint>

// ---------------------------------------------------------------------------
// SphericalExpansion, round 16: counting-sort CSR + chain-free gather.
//
// Scatter (82us champion) is pinned at the L2 atomic-RMW ceiling
// (~820MB RMW / 82us ~ LTS cap). R15 showed linked-list gather pays 2.6x
// slots in chain overhead. This round: CSR so the gather loop is a simple
// contiguous scan with prefetch — no pointer chase, no output atomics.
//
//   K_count: seg = 4*idx_i + z[idx_j]; gseg[e]=seg; cnt[seg]++ (spread 4B atomics)
//   K_scanA: per-256-block exclusive scan of cnt -> lpre, block sums -> bsum
//   K_scanB: 1 block scans 313 bsums -> boff
//   K_place: w = atomicAdd(&cnt[seg],-1)-1  (cnt returns to 0 -> replay-safe,
//            NO init kernel); csr[boff+lpre+w] = e
//   K_gather: warp per segment; edges contiguous; software-pipelined edge
//            prefetch; lane L owns floats {L,L+32,L+64,L+96} (lm=L&15,
//            n=(L>>4)+2k), 1 exp + compact-Y + 4 shfl + 4 FMA per edge,
//            register accumulators, 4 coalesced 128B stores per segment
//            (covers empty segments -> no zero-fill).
// ---------------------------------------------------------------------------

#define NSEG_MAX 80000
#define NSEG_PAD 80384          // 314 * 256
#define J_MAX    800000

__device__ int g_cnt[NSEG_MAX];     // zero at load; K_place restores to 0
__device__ int g_lpre[NSEG_PAD];    // block-local exclusive prefixes
__device__ int g_bsum[512];         // per-block totals
__device__ int g_boff[512];         // exclusive scan of block totals
__device__ int g_seg[J_MAX];        // seg id per edge
__device__ int g_csr[J_MAX];        // edge ids grouped by segment

// f1 selector: 0 = 1, 1 = x, 2 = y, 3 = z
__constant__ int cFS[16] = {0,2,3,1, 0,0,0,0, 0,2,1,2, 3,1,3,1};
// P,Q selectors for U1 = P*Q: 0 = x, 1 = y, 2 = z
__constant__ int cPQ[16][2] = {
    {0,0},{0,0},{0,0},{0,0},
    {0,1},{1,2},{0,0},{2,0},
    {0,0},{0,0},{1,2},{0,0},
    {0,0},{0,0},{0,0},{0,0},
};
// {C0, C1, C2}: Y = f1 * (C0 + C1*(P*Q) + C2*z2)  (y^2 removed via unit norm)
__constant__ float cC[16][3] = {
    { 0.28209479177387814f, 0.f,                 0.f},
    { 0.4886025119029199f,  0.f,                 0.f},
    { 0.4886025119029199f,  0.f,                 0.f},
    { 0.4886025119029199f,  0.f,                 0.f},
    { 0.f,                  1.0925484305920792f, 0.f},
    { 0.f,                  1.0925484305920792f, 0.f},
    {-0.31539156525252005f, 0.f,                 0.9461746957575602f},
    { 0.f,                  1.0925484305920792f, 0.f},
    {-0.5462742152960396f,  1.0925484305920792f, 0.5462742152960396f},
    {-0.5900435899266435f,  2.360174359706574f,  0.5900435899266435f},
    { 0.f,                  2.890611442640554f,  0.f},
    {-0.4570457994644658f,  0.f,                 2.285228997322329f},
    {-1.1195289977703462f,  0.f,                 1.865881662950577f},
    {-0.4570457994644658f,  0.f,                 2.285228997322329f},
    {-1.445305721320277f,   2.890611442640554f,  1.445305721320277f},
    {-1.7701307697799304f,  2.360174359706574f,  1.7701307697799304f},
};
__constant__ int cLM2L[16] = {0,1,1,1, 2,2,2,2, 2,3,3,3, 3,3,3,3};

#define K2E (-2.8853900817779268f)   // -2*log2(e)

__device__ __forceinline__ float ex2(float a) {
    float r; asm("ex2.approx.f32 %0, %1;" : "=f"(r) : "f"(a)); return r;
}
__device__ __forceinline__ float cutoff(float r) {
    const float u = __saturatef(fmaf(r, 2.0f, -9.0f));
    return fmaf(cospif(u), 0.5f, 0.5f);
}

// ---- K_count ----
__global__ void __launch_bounds__(256) count_kernel(
    const int* __restrict__ zspec,
    const int* __restrict__ idx_i,
    const int* __restrict__ idx_j,
    int J)
{
    int e = blockIdx.x * blockDim.x + threadIdx.x;
    if (e >= J) return;
    const int seg = (__ldg(idx_i + e) << 2) + __ldg(zspec + __ldg(idx_j + e));
    g_seg[e] = seg;
    atomicAdd(&g_cnt[seg], 1);
}

// ---- K_scanA: 256-wide block-local exclusive scan ----
__global__ void __launch_bounds__(256) scanA_kernel(int nseg) {
    __shared__ int sm[256];
    const int tid = threadIdx.x;
    const int s   = blockIdx.x * 256 + tid;
    const int v   = (s < nseg) ? g_cnt[s] : 0;
    sm[tid] = v;
    __syncthreads();
    #pragma unroll
    for (int off = 1; off < 256; off <<= 1) {
        const int t = (tid >= off) ? sm[tid - off] : 0;
        __syncthreads();
        sm[tid] += t;
        __syncthreads();
    }
    g_lpre[s] = sm[tid] - v;                 // exclusive
    if (tid == 255) g_bsum[blockIdx.x] = sm[255];
}

// ---- K_scanB: single block scans the block sums ----
__global__ void __launch_bounds__(512) scanB_kernel(int nblk) {
    __shared__ int sm[512];
    const int tid = threadIdx.x;
    const int v   = (tid < nblk) ? g_bsum[tid] : 0;
    sm[tid] = v;
    __syncthreads();
    #pragma unroll
    for (int off = 1; off < 512; off <<= 1) {
        const int t = (tid >= off) ? sm[tid - off] : 0;
        __syncthreads();
        sm[tid] += t;
        __syncthreads();
    }
    g_boff[tid] = sm[tid] - v;               // exclusive (valid for tid <= nblk)
}

// ---- K_place: scatter edge ids into CSR slots; cnt returns to 0 ----
__global__ void __launch_bounds__(256) place_kernel(int J) {
    int e = blockIdx.x * blockDim.x + threadIdx.x;
    if (e >= J) return;
    const int seg = g_seg[e];
    const int w   = atomicAdd(&g_cnt[seg], -1) - 1;    // unique slot [0,count)
    const int pos = g_boff[seg >> 8] + g_lpre[seg] + w;
    g_csr[pos] = e;
}

// ---- K_gather: warp per segment, contiguous edges, prefetch pipeline ----
__global__ void __launch_bounds__(256) gather_kernel(
    const float* __restrict__ dist,
    const float* __restrict__ dirs,      // [J,3]
    const float* __restrict__ centers,   // [32]
    float*       __restrict__ out,       // [nseg * 128]
    int nseg)
{
    const int lane  = threadIdx.x & 31;
    const int warp  = (blockIdx.x * blockDim.x + threadIdx.x) >> 5;
    const int nwarp = (gridDim.x * blockDim.x) >> 5;

    const int lm = lane & 15;
    const int h  = lane >> 4;
    const int l  = cLM2L[lm];

    const float cen = centers[lane];
    const float C0 = cC[lm][0], C1 = cC[lm][1], C2 = cC[lm][2];
    const int fs = cFS[lm];
    const int pi = cPQ[lm][0], qi = cPQ[lm][1];
    const bool f_y = (fs == 2), f_z = (fs == 3), f_one = (fs == 0);
    const bool p_y = (pi == 1), p_z = (pi == 2);
    const bool q_y = (qi == 1), q_z = (qi == 2);

    const int sR0 = 8*l + h;
    const int sR1 = sR0 + 2;
    const int sR2 = sR0 + 4;
    const int sR3 = sR0 + 6;

    const unsigned msk = 0xffffffffu;

    for (int s = warp; s < nseg; s += nwarp) {
        const int base = g_boff[s >> 8] + g_lpre[s];
        const int end  = g_boff[(s + 1) >> 8] + g_lpre[s + 1];
        const int n    = end - base;

        float a0 = 0.f, a1 = 0.f, a2 = 0.f, a3 = 0.f;

        // software pipeline: prefetch edge k+1 while computing edge k
        int e = (n > 0) ? __ldg(g_csr + base) : 0;
        float r = __ldg(dist + e);
        float x = __ldg(dirs + 3*e + 0);
        float y = __ldg(dirs + 3*e + 1);
        float z = __ldg(dirs + 3*e + 2);

        for (int k = 0; k < n; k++) {
            const int  e2 = (k + 1 < n) ? __ldg(g_csr + base + k + 1) : 0;
            const float r2 = __ldg(dist + e2);
            const float x2 = __ldg(dirs + 3*e2 + 0);
            const float y2 = __ldg(dirs + 3*e2 + 1);
            const float z2 = __ldg(dirs + 3*e2 + 2);

            // rb for this lane's center, cutoff folded in
            const float t  = r - cen;
            const float rb = ex2(K2E * t * t) * cutoff(r);

            // Y = f1 * (C0 + C1*P*Q + C2*z^2) for this lane's lm
            const float Pv = p_y ? y : (p_z ? z : x);
            const float Qv = q_y ? y : (q_z ? z : x);
            const float f2 = fmaf(C1, Pv * Qv, fmaf(C2, z * z, C0));
            const float F1 = f_y ? y : (f_z ? z : x);
            const float Y  = f_one ? f2 : F1 * f2;

            const float R0 = __shfl_sync(msk, rb, sR0);
            const float R1 = __shfl_sync(msk, rb, sR1);
            const float R2 = __shfl_sync(msk, rb, sR2);
            const float R3 = __shfl_sync(msk, rb, sR3);

            a0 = fmaf(Y, R0, a0);
            a1 = fmaf(Y, R1, a1);
            a2 = fmaf(Y, R2, a2);
            a3 = fmaf(Y, R3, a3);

            r = r2; x = x2; y = y2; z = z2;
        }

        // coalesced stores; empty segments write zeros (no zero-fill kernel)
        float* p = out + ((size_t)s << 7) + lane;
        p[0]  = a0;
        p[32] = a1;
        p[64] = a2;
        p[96] = a3;
    }
}

extern "C" void kernel_launch(void* const* d_in, const int* in_sizes, int n_in,
                              void* d_out, int out_size) {
    const float* dist    = (const float*)d_in[0];
    const float* dirs    = (const float*)d_in[1];
    const float* centers = (const float*)d_in[2];
    const int*   zspec   = (const int*)d_in[3];
    const int*   idx_i   = (const int*)d_in[4];
    const int*   idx_j   = (const int*)d_in[5];
    float*       out     = (float*)d_out;
    const int J    = in_sizes[0];
    const int nseg = out_size >> 7;              // 128 floats per segment
    const int nblk = (nseg + 255) >> 8;          // scanA blocks (<= 512)

    count_kernel<<<(J + 255) / 256, 256>>>(zspec, idx_i, idx_j, J);
    scanA_kernel<<<nblk, 256>>>(nseg);
    scanB_kernel<<<1, 512>>>(nblk);
    place_kernel<<<(J + 255) / 256, 256>>>(J);

    int nsm = 148, occ = 6;
    cudaDeviceGetAttribute(&nsm, cudaDevAttrMultiProcessorCount, 0);
    cudaOccupancyMaxActiveBlocksPerMultiprocessor(&occ, gather_kernel, 256, 0);
    if (occ < 1) occ = 1;
    gather_kernel<<<nsm * occ, 256>>>(dist, dirs, centers, out, nseg);
}

// round 17
// speedup vs baseline: 2.0365x; 1.7270x over previous
#include <cuda_runtime.h>
#include <cstdint>

// ---------------------------------------------------------------------------
// SphericalExpansion, round 17: CSR v2 — lane-parallel edge fetch.
//
// R16 lesson: CSR gather was serial-latency bound (5 dependent scalar loads
// per edge). Fix: lanes load a whole 32-edge chunk of the segment in
// PARALLEL (5 LDG per chunk), then broadcast each edge's (r,x,y,z) to the
// warp with 4 dynamic-lane shuffles -> per-edge cost is pure compute.
//
//   K_count: (4 edges/thread, int4) seg=4*idx_i+z[idx_j]; g_seg[e]=seg; cnt++
//   K_scanA/B: two-level exclusive scan of cnt (80k, 256/block + 313 sums)
//   K_place: (4 edges/thread) w=atomicAdd(&cnt,-1)-1 (cnt->0, replay-safe);
//            csr[boff+lpre+w]=e
//   K_gather: warp per segment (grid-stride). Lane L owns floats
//            {L,L+32,L+64,L+96} (lm=L&15, n=(L>>4)+2k). Register accum,
//            4 coalesced 128B stores. No output atomics, no zero-fill.
// ---------------------------------------------------------------------------

#define NSEG_PAD 80640          // >= (ceil(nseg/256)+1)*256
#define J_MAX    800000

__device__ int g_cnt[NSEG_PAD];     // zero at load; K_place restores to 0
__device__ int g_lpre[NSEG_PAD];
__device__ int g_bsum[512];
__device__ int g_boff[512];
__device__ int g_seg[J_MAX];
__device__ int g_csr[J_MAX];

// f1 selector: 0 = 1, 1 = x, 2 = y, 3 = z
__constant__ int cFS[16] = {0,2,3,1, 0,0,0,0, 0,2,1,2, 3,1,3,1};
// P,Q selectors for U1 = P*Q: 0 = x, 1 = y, 2 = z
__constant__ int cPQ[16][2] = {
    {0,0},{0,0},{0,0},{0,0},
    {0,1},{1,2},{0,0},{2,0},
    {0,0},{0,0},{1,2},{0,0},
    {0,0},{0,0},{0,0},{0,0},
};
// {C0, C1, C2}: Y = f1 * (C0 + C1*(P*Q) + C2*z2)  (y^2 removed via unit norm)
__constant__ float cC[16][3] = {
    { 0.28209479177387814f, 0.f,                 0.f},
    { 0.4886025119029199f,  0.f,                 0.f},
    { 0.4886025119029199f,  0.f,                 0.f},
    { 0.4886025119029199f,  0.f,                 0.f},
    { 0.f,                  1.0925484305920792f, 0.f},
    { 0.f,                  1.0925484305920792f, 0.f},
    {-0.31539156525252005f, 0.f,                 0.9461746957575602f},
    { 0.f,                  1.0925484305920792f, 0.f},
    {-0.5462742152960396f,  1.0925484305920792f, 0.5462742152960396f},
    {-0.5900435899266435f,  2.360174359706574f,  0.5900435899266435f},
    { 0.f,                  2.890611442640554f,  0.f},
    {-0.4570457994644658f,  0.f,                 2.285228997322329f},
    {-1.1195289977703462f,  0.f,                 1.865881662950577f},
    {-0.4570457994644658f,  0.f,                 2.285228997322329f},
    {-1.445305721320277f,   2.890611442640554f,  1.445305721320277f},
    {-1.7701307697799304f,  2.360174359706574f,  1.7701307697799304f},
};
__constant__ int cLM2L[16] = {0,1,1,1, 2,2,2,2, 2,3,3,3, 3,3,3,3};

#define K2E (-2.8853900817779268f)   // -2*log2(e)

__device__ __forceinline__ float ex2(float a) {
    float r; asm("ex2.approx.f32 %0, %1;" : "=f"(r) : "f"(a)); return r;
}
__device__ __forceinline__ float cutoff(float r) {
    const float u = __saturatef(fmaf(r, 2.0f, -9.0f));
    return fmaf(cospif(u), 0.5f, 0.5f);
}

// ---- K_count: 4 edges/thread ----
__global__ void __launch_bounds__(256) count_kernel(
    const int* __restrict__ zspec,
    const int* __restrict__ idx_i,
    const int* __restrict__ idx_j,
    int J)
{
    const int tq = blockIdx.x * blockDim.x + threadIdx.x;
    const int e0 = tq << 2;
    if (e0 + 3 < J) {
        const int4 i4 = __ldg((const int4*)idx_i + tq);
        const int4 j4 = __ldg((const int4*)idx_j + tq);
        int4 sg;
        sg.x = (i4.x << 2) + __ldg(zspec + j4.x);
        sg.y = (i4.y << 2) + __ldg(zspec + j4.y);
        sg.z = (i4.z << 2) + __ldg(zspec + j4.z);
        sg.w = (i4.w << 2) + __ldg(zspec + j4.w);
        *((int4*)g_seg + tq) = sg;
        atomicAdd(&g_cnt[sg.x], 1);
        atomicAdd(&g_cnt[sg.y], 1);
        atomicAdd(&g_cnt[sg.z], 1);
        atomicAdd(&g_cnt[sg.w], 1);
    } else {
        for (int e = e0; e < J; e++) {
            const int s = (__ldg(idx_i + e) << 2) + __ldg(zspec + __ldg(idx_j + e));
            g_seg[e] = s;
            atomicAdd(&g_cnt[s], 1);
        }
    }
}

// ---- K_scanA: 256-wide block-local exclusive scan ----
__global__ void __launch_bounds__(256) scanA_kernel(int nseg) {
    __shared__ int sm[256];
    const int tid = threadIdx.x;
    const int s   = blockIdx.x * 256 + tid;
    const int v   = (s < nseg) ? g_cnt[s] : 0;
    sm[tid] = v;
    __syncthreads();
    #pragma unroll
    for (int off = 1; off < 256; off <<= 1) {
        const int t = (tid >= off) ? sm[tid - off] : 0;
        __syncthreads();
        sm[tid] += t;
        __syncthreads();
    }
    g_lpre[s] = sm[tid] - v;
    if (tid == 255) g_bsum[blockIdx.x] = sm[255];
}

// ---- K_scanB ----
__global__ void __launch_bounds__(512) scanB_kernel(int nblk) {
    __shared__ int sm[512];
    const int tid = threadIdx.x;
    const int v   = (tid < nblk) ? g_bsum[tid] : 0;
    sm[tid] = v;
    __syncthreads();
    #pragma unroll
    for (int off = 1; off < 512; off <<= 1) {
        const int t = (tid >= off) ? sm[tid - off] : 0;
        __syncthreads();
        sm[tid] += t;
        __syncthreads();
    }
    g_boff[tid] = sm[tid] - v;
}

// ---- K_place: 4 edges/thread (4 independent atomic chains) ----
__global__ void __launch_bounds__(256) place_kernel(int J) {
    const int tq = blockIdx.x * blockDim.x + threadIdx.x;
    const int e0 = tq << 2;
    if (e0 + 3 < J) {
        const int4 sg = *((const int4*)g_seg + tq);
        const int w0 = atomicAdd(&g_cnt[sg.x], -1) - 1;
        const int w1 = atomicAdd(&g_cnt[sg.y], -1) - 1;
        const int w2 = atomicAdd(&g_cnt[sg.z], -1) - 1;
        const int w3 = atomicAdd(&g_cnt[sg.w], -1) - 1;
        g_csr[g_boff[sg.x >> 8] + g_lpre[sg.x] + w0] = e0 + 0;
        g_csr[g_boff[sg.y >> 8] + g_lpre[sg.y] + w1] = e0 + 1;
        g_csr[g_boff[sg.z >> 8] + g_lpre[sg.z] + w2] = e0 + 2;
        g_csr[g_boff[sg.w >> 8] + g_lpre[sg.w] + w3] = e0 + 3;
    } else {
        for (int e = e0; e < J; e++) {
            const int s = g_seg[e];
            const int w = atomicAdd(&g_cnt[s], -1) - 1;
            g_csr[g_boff[s >> 8] + g_lpre[s] + w] = e;
        }
    }
}

// ---- K_gather: warp/segment; lane-parallel fetch + shuffle broadcast ----
__global__ void __launch_bounds__(256) gather_kernel(
    const float* __restrict__ dist,
    const float* __restrict__ dirs,      // [J,3]
    const float* __restrict__ centers,   // [32]
    float*       __restrict__ out,       // [nseg * 128]
    int nseg)
{
    const int lane  = threadIdx.x & 31;
    const int warp  = (blockIdx.x * blockDim.x + threadIdx.x) >> 5;
    const int nwarp = (gridDim.x * blockDim.x) >> 5;

    const int lm = lane & 15;
    const int h  = lane >> 4;
    const int l  = cLM2L[lm];

    const float cen = centers[lane];
    const float C0 = cC[lm][0], C1 = cC[lm][1], C2 = cC[lm][2];
    const int fs = cFS[lm];
    const int pi = cPQ[lm][0], qi = cPQ[lm][1];
    const bool f_y = (fs == 2), f_z = (fs == 3), f_one = (fs == 0);
    const bool p_y = (pi == 1), p_z = (pi == 2);
    const bool q_y = (qi == 1), q_z = (qi == 2);

    const int sR0 = 8*l + h;
    const int sR1 = sR0 + 2;
    const int sR2 = sR0 + 4;
    const int sR3 = sR0 + 6;

    const unsigned msk = 0xffffffffu;

    for (int s = warp; s < nseg; s += nwarp) {
        const int base = g_boff[s >> 8] + g_lpre[s];
        const int end  = g_boff[(s + 1) >> 8] + g_lpre[s + 1];
        const int n    = end - base;

        float a0 = 0.f, a1 = 0.f, a2 = 0.f, a3 = 0.f;

        for (int k0 = 0; k0 < n; k0 += 32) {
            const int m = min(32, n - k0);

            // lane-parallel fetch of up to 32 edges of this segment
            const bool act = (lane < m);
            const int  e   = act ? __ldg(g_csr + base + k0 + lane) : 0;
            const float my_r = __ldg(dist + e);
            const float my_x = __ldg(dirs + 3*e + 0);
            const float my_y = __ldg(dirs + 3*e + 1);
            const float my_z = __ldg(dirs + 3*e + 2);

            for (int k = 0; k < m; k++) {
                // broadcast edge k's data from lane k
                const float r = __shfl_sync(msk, my_r, k);
                const float x = __shfl_sync(msk, my_x, k);
                const float y = __shfl_sync(msk, my_y, k);
                const float z = __shfl_sync(msk, my_z, k);

                // rb for this lane's center, cutoff folded in
                const float t  = r - cen;
                const float rb = ex2(K2E * t * t) * cutoff(r);

                // Y = f1 * (C0 + C1*P*Q + C2*z^2)
                const float Pv = p_y ? y : (p_z ? z : x);
                const float Qv = q_y ? y : (q_z ? z : x);
                const float f2 = fmaf(C1, Pv * Qv, fmaf(C2, z * z, C0));
                const float F1 = f_y ? y : (f_z ? z : x);
                const float Y  = f_one ? f2 : F1 * f2;

                const float R0 = __shfl_sync(msk, rb, sR0);
                const float R1 = __shfl_sync(msk, rb, sR1);
                const float R2 = __shfl_sync(msk, rb, sR2);
                const float R3 = __shfl_sync(msk, rb, sR3);

                a0 = fmaf(Y, R0, a0);
                a1 = fmaf(Y, R1, a1);
                a2 = fmaf(Y, R2, a2);
                a3 = fmaf(Y, R3, a3);
            }
        }

        // coalesced stores; empty segments write zeros
        float* p = out + ((size_t)s << 7) + lane;
        p[0]  = a0;
        p[32] = a1;
        p[64] = a2;
        p[96] = a3;
    }
}

extern "C" void kernel_launch(void* const* d_in, const int* in_sizes, int n_in,
                              void* d_out, int out_size) {
    const float* dist    = (const float*)d_in[0];
    const float* dirs    = (const float*)d_in[1];
    const float* centers = (const float*)d_in[2];
    const int*   zspec   = (const int*)d_in[3];
    const int*   idx_i   = (const int*)d_in[4];
    const int*   idx_j   = (const int*)d_in[5];
    float*       out     = (float*)d_out;
    const int J    = in_sizes[0];
    const int nseg = out_size >> 7;
    const int nblk = (nseg + 255) >> 8;
    const int nquad = (J + 3) >> 2;

    count_kernel<<<(nquad + 255) / 256, 256>>>(zspec, idx_i, idx_j, J);
    scanA_kernel<<<nblk, 256>>>(nseg);
    scanB_kernel<<<1, 512>>>(nblk);
    place_kernel<<<(nquad + 255) / 256, 256>>>(J);

    int nsm = 148, occ = 6;
    cudaDeviceGetAttribute(&nsm, cudaDevAttrMultiProcessorCount, 0);
    cudaOccupancyMaxActiveBlocksPerMultiprocessor(&occ, gather_kernel, 256, 0);
    if (occ < 1) occ = 1;
    gather_kernel<<<nsm * occ, 256>>>(dist, dirs, centers, out, nseg);
}